// round 3
// baseline (speedup 1.0000x reference)
#include <cuda_runtime.h>
#include <cuda_bf16.h>

#define N_ATOMS 40000
#define N_PAIRS 640000
#define DD 128
#define RR 20

// Scratch (allocation-free rule: static device globals)
__device__ float g_h[N_ATOMS * DD];    // 20.48 MB
__device__ float g_agg[N_ATOMS * DD];  // 20.48 MB

// Packed fp32x2 FMA (Blackwell f32x2 pipe; ptxas never auto-fuses this)
#define FFMA2(acc, a, b) \
    asm("fma.rn.f32x2 %0, %1, %2, %0;" : "+l"(acc) : "l"(a), "l"(b))

__device__ __forceinline__ unsigned long long pack2(float x, float y) {
    unsigned long long d;
    asm("mov.b64 %0, {%1,%2};" : "=l"(d) : "f"(x), "f"(y));
    return d;
}
__device__ __forceinline__ void unpack2(unsigned long long d, float& x, float& y) {
    asm("mov.b64 {%0,%1}, %2;" : "=f"(x), "=f"(y) : "l"(d));
}

// Vector global reduction, ISA-level (no dependence on CUDA header overloads).
__device__ __forceinline__ void red_add_v4(float* addr, float a, float b,
                                           float c, float d) {
    asm volatile("red.global.add.v4.f32 [%0], {%1, %2, %3, %4};"
                 :: "l"(addr), "f"(a), "f"(b), "f"(c), "f"(d) : "memory");
}

__device__ __forceinline__ float sspf(float x) {
    float sp = (x > 15.f) ? x : __logf(1.f + __expf(x));
    return sp - 0.69314718055994531f;
}

__global__ void zero_kernel(float4* __restrict__ p, int n4) {
    int i = blockIdx.x * blockDim.x + threadIdx.x;
    if (i < n4) p[i] = make_float4(0.f, 0.f, 0.f, 0.f);
}

// -----------------------------------------------------------------------------
// Tiled SGEMM with f32x2 packed math:
// out[M,128] = A[M,128] @ W[128,128]^T + bias, optional ssp epilogue.
// BM=64, BN=128, BK=16, 256 threads; per thread 8 rows x 4 cols, accumulated
// as 4 row-pairs x 4 cols in packed f32x2.
// -----------------------------------------------------------------------------
template <bool SSP>
__global__ __launch_bounds__(256) void gemm_atoms(
    const float* __restrict__ A, const float* __restrict__ W,
    const float* __restrict__ bias, float* __restrict__ out, int M)
{
    __shared__ float As[16][68];    // [k][row], padded; row stride 272B (8B-mult)
    __shared__ float Bs[16][132];   // [k][col], padded; row stride 528B (16B-mult)

    const int tid  = threadIdx.x;
    const int tcol = tid & 31;      // cols 4*tcol .. 4*tcol+3
    const int trow = tid >> 5;      // rows 8*trow .. 8*trow+7
    const int a0   = blockIdx.x * 64;

    unsigned long long accp[4][4];  // [row-pair][col], lo = even row, hi = odd
#pragma unroll
    for (int p = 0; p < 4; p++)
#pragma unroll
        for (int j = 0; j < 4; j++) accp[p][j] = 0ull;

    for (int kt = 0; kt < 128; kt += 16) {
        // A tile: 64 rows x 16 k
        {
            int r = tid >> 2, kg = (tid & 3) << 2;
            float4 v = *(const float4*)&A[(size_t)(a0 + r) * 128 + kt + kg];
            As[kg + 0][r] = v.x; As[kg + 1][r] = v.y;
            As[kg + 2][r] = v.z; As[kg + 3][r] = v.w;
        }
        // W tile: 128 cols x 16 k
#pragma unroll
        for (int q = 0; q < 2; q++) {
            int idx = tid + q * 256;
            int c = idx >> 2, kg = (idx & 3) << 2;
            float4 v = *(const float4*)&W[(size_t)c * 128 + kt + kg];
            Bs[kg + 0][c] = v.x; Bs[kg + 1][c] = v.y;
            Bs[kg + 2][c] = v.z; Bs[kg + 3][c] = v.w;
        }
        __syncthreads();
#pragma unroll
        for (int k = 0; k < 16; k++) {
            float4 b = *(const float4*)&Bs[k][tcol * 4];
            unsigned long long bb[4];
            bb[0] = pack2(b.x, b.x); bb[1] = pack2(b.y, b.y);
            bb[2] = pack2(b.z, b.z); bb[3] = pack2(b.w, b.w);
            const unsigned long long* ap =
                (const unsigned long long*)&As[k][trow * 8];
            unsigned long long a[4];
            a[0] = ap[0]; a[1] = ap[1]; a[2] = ap[2]; a[3] = ap[3];
#pragma unroll
            for (int p = 0; p < 4; p++)
#pragma unroll
                for (int j = 0; j < 4; j++) FFMA2(accp[p][j], a[p], bb[j]);
        }
        __syncthreads();
    }

    float4 bia = *(const float4*)&bias[tcol * 4];
    float bb[4] = {bia.x, bia.y, bia.z, bia.w};
#pragma unroll
    for (int p = 0; p < 4; p++) {
        float lo[4], hi[4];
#pragma unroll
        for (int j = 0; j < 4; j++) {
            unpack2(accp[p][j], lo[j], hi[j]);
            lo[j] += bb[j]; hi[j] += bb[j];
            if (SSP) { lo[j] = sspf(lo[j]); hi[j] = sspf(hi[j]); }
        }
        size_t r0 = (size_t)(a0 + trow * 8 + 2 * p) * 128 + tcol * 4;
        *(float4*)&out[r0]       = make_float4(lo[0], lo[1], lo[2], lo[3]);
        *(float4*)&out[r0 + 128] = make_float4(hi[0], hi[1], hi[2], hi[3]);
    }
}

// -----------------------------------------------------------------------------
// Fused pair kernel: Wij = ssp(f_ij @ W_f^T + b_f) * rcut;
//                    agg[idx_i] += h[idx_j] * Wij   (vector-atomic scatter)
// 256 threads = 8 warps. One warp per pair; each thread owns 4 channels.
// Filter dot packed along K (f32x2). Gather LDG.128, scatter RED.128.
// -----------------------------------------------------------------------------
__global__ __launch_bounds__(256) void pair_kernel(
    const float* __restrict__ f_ij, const int* __restrict__ idx_i,
    const int* __restrict__ idx_j, const float* __restrict__ rcut,
    const float* __restrict__ W_f, const float* __restrict__ b_f,
    const float* __restrict__ h, float* __restrict__ agg)
{
    __shared__ __align__(16) float sF[32 * RR];   // 32 pairs x 20 rbf = 2.5KB
    __shared__ float sR[32];
    __shared__ int   sI[32];
    __shared__ int   sJ[32];

    const int tid  = threadIdx.x;
    const int lane = tid & 31;
    const int warp = tid >> 5;     // 0..7
    const int c0   = lane * 4;     // this thread's 4 channels

    // Per-thread packed filter weights: wk[c][k2] = {W_f[c0+c][2k2], [2k2+1]}
    // W_f rows are 80B = 5x16B, so every row is 16B-aligned.
    unsigned long long wk[4][10];
    float bf[4];
#pragma unroll
    for (int c = 0; c < 4; c++) {
        const float2* row = (const float2*)&W_f[(c0 + c) * RR];
#pragma unroll
        for (int k = 0; k < 10; k++) {
            float2 v = __ldg(&row[k]);
            wk[c][k] = pack2(v.x, v.y);
        }
        bf[c] = __ldg(&b_f[c0 + c]);
    }

    const int nchunks = N_PAIRS / 32;
    for (int ch = blockIdx.x; ch < nchunks; ch += gridDim.x) {
        const int base = ch * 32;
        __syncthreads();   // protect smem reuse across iterations
        if (tid < 160) {
            ((float4*)sF)[tid] = ((const float4*)&f_ij[(size_t)base * RR])[tid];
        } else if (tid < 192) {
            int q = tid - 160;
            sR[q] = rcut[base + q];
            sI[q] = idx_i[base + q];
            sJ[q] = idx_j[base + q];
        }
        __syncthreads();

#pragma unroll
        for (int qq = 0; qq < 4; qq++) {
            const int q = warp * 4 + qq;      // this warp's pair
            // f row broadcast: 10x LDS.64, already packed for f32x2
            const unsigned long long* fq =
                (const unsigned long long*)&sF[q * RR];   // q*80B, 8B-aligned
            unsigned long long f[10];
#pragma unroll
            for (int k = 0; k < 10; k++) f[k] = fq[k];

            float w[4];
#pragma unroll
            for (int c = 0; c < 4; c++) {
                unsigned long long acc = 0ull;   // {0.f, 0.f}
#pragma unroll
                for (int k = 0; k < 10; k++) FFMA2(acc, f[k], wk[c][k]);
                float lo, hi;
                unpack2(acc, lo, hi);
                w[c] = sspf(lo + hi + bf[c]) * sR[q];
            }

            const float4 hv = *(const float4*)&h[(size_t)sJ[q] * DD + c0];
            red_add_v4(&agg[(size_t)sI[q] * DD + c0],
                       hv.x * w[0], hv.y * w[1], hv.z * w[2], hv.w * w[3]);
        }
    }
}

extern "C" void kernel_launch(void* const* d_in, const int* in_sizes, int n_in,
                              void* d_out, int out_size)
{
    const float* x     = (const float*)d_in[0];
    const float* f_ij  = (const float*)d_in[1];
    const int*   idx_i = (const int*)d_in[2];
    const int*   idx_j = (const int*)d_in[3];
    const float* rcut  = (const float*)d_in[4];
    const float* W_in  = (const float*)d_in[5];
    const float* b_in  = (const float*)d_in[6];
    const float* W_f   = (const float*)d_in[7];
    const float* b_f   = (const float*)d_in[8];
    const float* W_out = (const float*)d_in[9];
    const float* b_out = (const float*)d_in[10];
    float* out = (float*)d_out;

    float* hptr = nullptr;
    float* aptr = nullptr;
    cudaGetSymbolAddress((void**)&hptr, g_h);
    cudaGetSymbolAddress((void**)&aptr, g_agg);

    const int n4 = N_ATOMS * DD / 4;
    zero_kernel<<<(n4 + 255) / 256, 256>>>((float4*)aptr, n4);
    gemm_atoms<false><<<N_ATOMS / 64, 256>>>(x, W_in, b_in, hptr, N_ATOMS);
    pair_kernel<<<1184, 256>>>(f_ij, idx_i, idx_j, rcut, W_f, b_f, hptr, aptr);
    gemm_atoms<true><<<N_ATOMS / 64, 256>>>(aptr, W_out, b_out, out, N_ATOMS);
}